// round 11
// baseline (speedup 1.0000x reference)
#include <cuda_runtime.h>
#include <cuda_fp16.h>
#include <cstdint>

// ---------------- Problem constants ----------------
#define BATCH   16
#define CIN     32
#define WH_IN   224
#define WH_OUT  222
#define COUT    64
#define KSTEPS  18
#define NTILES  (BATCH * WH_OUT * 2)     // 7104 = 148*48
#define TILES_PER_CTA 48
#define OPLANE  (BATCH * WH_OUT * WH_OUT)
#define NTHREADS 640

// ---------------- SMEM layout ----------------
// A: ring of 6 y-row slots, each [16 chan-pairs][AST u32 cols] fp16x2.
// AST = 136: 136 % 32 == 8 -> A LDS banks 8q+r conflict-free; %4==0 -> STS.128 ok.
#define AST        136
#define SLOT_BYTES (16 * AST * 4)        // 8704
#define NSLOTS     6
#define A_BYTES    (NSLOTS * SLOT_BYTES) // 52224
#define SM_B       A_BYTES
// B row: 72 v2-slots (8B); stride 672B -> 168 words == 8 (mod 32):
// per 16-lane LDS.64 phase, words r*8 + 2q + {0,1} = 0..31 all distinct.
#define BSTR       672
#define SMEM_BYTES (SM_B + COUT * BSTR)  // 95232

// Barrier ids: full[it&3] = 1..4 (384), empty[it&3] = 5..8 (384), rendezvous = 9 (640)
#define BAR_SYNC(id, n)   asm volatile("bar.sync %0, %1;"   :: "r"(id), "r"(n) : "memory")
#define BAR_ARRIVE(id, n) asm volatile("bar.arrive %0, %1;" :: "r"(id), "r"(n) : "memory")
#define MEMBAR_CTA()      asm volatile("membar.cta;" ::: "memory")

// ---------------- helpers ----------------
static __device__ __forceinline__ uint32_t smem_u32(const void* p) {
    uint32_t a;
    asm("{ .reg .u64 t; cvta.to.shared.u64 t, %1; cvt.u32.u64 %0, t; }" : "=r"(a) : "l"(p));
    return a;
}
static __device__ __forceinline__ uint32_t lds_u32(uint32_t a) {
    uint32_t v; asm volatile("ld.shared.b32 %0, [%1];" : "=r"(v) : "r"(a)); return v;
}
static __device__ __forceinline__ void lds_u64(uint32_t a, uint32_t* v) {
    asm volatile("ld.shared.v2.b32 {%0,%1}, [%2];" : "=r"(v[0]), "=r"(v[1]) : "r"(a));
}
static __device__ __forceinline__ void sts_u64(uint32_t a, const uint32_t* v) {
    asm volatile("st.shared.v2.b32 [%0], {%1,%2};" :: "r"(a), "r"(v[0]), "r"(v[1]));
}
static __device__ __forceinline__ void sts_u128(uint32_t a, const uint32_t* v) {
    asm volatile("st.shared.v4.b32 [%0], {%1,%2,%3,%4};"
                 :: "r"(a), "r"(v[0]), "r"(v[1]), "r"(v[2]), "r"(v[3]));
}
// pack two f32 -> f16x2 word: LOW half = v0, HIGH half = v1
static __device__ __forceinline__ uint32_t pack_f16x2(float v0, float v1) {
    uint32_t w;
    asm("cvt.rn.f16x2.f32 %0, %1, %2;" : "=r"(w) : "f"(v1), "f"(v0));
    return w;
}
static __device__ __forceinline__ void mma_f16(float* d, const uint32_t* a,
                                               uint32_t b0, uint32_t b1) {
    asm volatile(
        "mma.sync.aligned.m16n8k16.row.col.f32.f16.f16.f32 "
        "{%0,%1,%2,%3}, {%4,%5,%6,%7}, {%8,%9}, {%0,%1,%2,%3};"
        : "+f"(d[0]), "+f"(d[1]), "+f"(d[2]), "+f"(d[3])
        : "r"(a[0]), "r"(a[1]), "r"(a[2]), "r"(a[3]), "r"(b0), "r"(b1));
}

// Stage one input row (16 chan-pairs x 132 cols) into its ring slot.
// All global loads issued first (MLP ~10), then convert + STS.
static __device__ __forceinline__ void stage_row(const float* __restrict__ x,
                                                 int b, int xs, int yr,
                                                 uint32_t a_sm, int ptid) {
    const uint32_t slot = a_sm + (uint32_t)((yr % NSLOTS) * SLOT_BYTES);
    float4 f0[5], f1[5];
    #pragma unroll
    for (int i = 0; i < 5; ++i) {
        const int u = ptid + i * 128;
        if (u < 528) {
            const int c2 = u / 33;
            const int q4 = u - c2 * 33;
            const float* gp = x + ((size_t)(b * CIN + 2 * c2) * WH_IN + yr) * WH_IN
                                + xs + q4 * 4;
            f0[i] = *(const float4*)gp;
            f1[i] = *(const float4*)(gp + WH_IN * WH_IN);
        }
    }
    #pragma unroll
    for (int i = 0; i < 5; ++i) {
        const int u = ptid + i * 128;
        if (u < 528) {
            const int c2 = u / 33;
            const int q4 = u - c2 * 33;
            uint32_t hv[4];
            hv[0] = pack_f16x2(f0[i].x, f1[i].x);
            hv[1] = pack_f16x2(f0[i].y, f1[i].y);
            hv[2] = pack_f16x2(f0[i].z, f1[i].z);
            hv[3] = pack_f16x2(f0[i].w, f1[i].w);
            sts_u128(slot + (uint32_t)((c2 * AST + q4 * 4) * 4), hv);
        }
    }
}

__global__ void __launch_bounds__(NTHREADS, 1)
quanv_w20_kernel(const float* __restrict__ x, const float* __restrict__ w,
                 float* __restrict__ out)
{
    extern __shared__ char smem[];
    const uint32_t sbase = smem_u32(smem);
    const uint32_t a_sm  = sbase;
    const uint32_t b_sm  = sbase + SM_B;

    const int tid = threadIdx.x;
    const int wid = tid >> 5;
    const int lid = tid & 31;
    const int t0  = blockIdx.x * TILES_PER_CTA;

    // ---- one-time: build B = fp16(w), v2 slots {bh(h0), bh(h1)} ----
    #pragma unroll 1
    for (int u = tid; u < COUT * 72; u += NTHREADS) {
        const int n   = u / 72;
        const int rem = u - n * 72;
        const int ks  = rem >> 2;
        const int qq  = rem & 3;
        const int tap = ks % 9, ch = ks / 9;
        uint32_t bw[2];
        #pragma unroll
        for (int h = 0; h < 2; ++h) {
            const int c = 2 * (ch * 8 + qq + 4 * h);
            bw[h] = pack_f16x2(w[n * 288 + c * 9 + tap], w[n * 288 + (c + 1) * 9 + tap]);
        }
        sts_u64(b_sm + (uint32_t)(n * BSTR + rem * 8), bw);
    }
    __syncthreads();

    if (wid < 16) {
        // ==== CONSUMERS: 2 teams x 8 warps; warp = M32 x N32 ====
        const int team  = wid >> 3;       // warps 0-7 team0, 8-15 team1
        const int w8    = wid & 7;
        const int wx    = w8 & 3;         // M-quarter (32 px)
        const int nhalf = w8 >> 2;        // N-half (32 ch)
        const int r = lid >> 2, q = lid & 3;
        const uint32_t bb = b_sm + (uint32_t)((nhalf * 32 + r) * BSTR + q * 8);

        uint32_t ab[2][2];
        #pragma unroll
        for (int j = 0; j < 2; ++j)
            #pragma unroll
            for (int h = 0; h < 2; ++h)
                ab[j][h] = a_sm + (uint32_t)(q * AST + wx * 32 + j * 16 + r + 8 * h) * 4;

        #pragma unroll 1
        for (int it = team; it < TILES_PER_CTA; it += 2) {
            const int t    = t0 + it;
            const int g    = t / WH_OUT;
            const int y    = t - g * WH_OUT;
            const int b    = g >> 1;
            const int half = g & 1;
            const int x0   = half ? 94 : 0;
            const int xoff = half ? 2 : 0;

            if ((y == 0 && it > 0) || (y == 1 && it > 1))
                BAR_SYNC(9, NTHREADS);            // boundary rendezvous
            BAR_SYNC(1 + (it & 3), 384);          // rows staged for tile it

            uint32_t sl[3];
            #pragma unroll
            for (int d = 0; d < 3; ++d)
                sl[d] = (uint32_t)(((y + d) % NSLOTS) * SLOT_BYTES) + (uint32_t)(xoff * 4);

            float acc[2][4][4];
            #pragma unroll
            for (int j = 0; j < 2; ++j)
                #pragma unroll
                for (int nb = 0; nb < 4; ++nb)
                    #pragma unroll
                    for (int e = 0; e < 4; ++e) acc[j][nb][e] = 0.0f;

            #pragma unroll
            for (int ks = 0; ks < KSTEPS; ++ks) {
                const int tap = ks % 9, ch = ks / 9;
                const uint32_t off = sl[tap / 3] + (uint32_t)(ch * 8 * AST * 4 + (tap % 3) * 4);
                uint32_t ahi[2][4];
                #pragma unroll
                for (int j = 0; j < 2; ++j) {
                    ahi[j][0] = lds_u32(ab[j][0] + off);
                    ahi[j][1] = lds_u32(ab[j][1] + off);
                    ahi[j][2] = lds_u32(ab[j][0] + off + 4 * AST * 4);
                    ahi[j][3] = lds_u32(ab[j][1] + off + 4 * AST * 4);
                }
                #pragma unroll
                for (int nb = 0; nb < 4; ++nb) {
                    uint32_t bq[2];
                    lds_u64(bb + (uint32_t)(nb * 8 * BSTR + ks * 32), bq);
                    #pragma unroll
                    for (int j = 0; j < 2; ++j)
                        mma_f16(acc[j][nb], ahi[j], bq[0], bq[1]);   // x * fp16(W)
                }
            }

            BAR_ARRIVE(5 + (it & 3), 384);        // smem reads done (ring class)

            float* ob = out + ((size_t)b * WH_OUT + y) * WH_OUT
                            + (size_t)(nhalf * 32 + 2 * q) * OPLANE;
            #pragma unroll
            for (int j = 0; j < 2; ++j)
                #pragma unroll
                for (int h = 0; h < 2; ++h) {
                    const int px = x0 + wx * 32 + j * 16 + r + 8 * h;
                    #pragma unroll
                    for (int nb = 0; nb < 4; ++nb) {
                        ob[(size_t)(nb * 8) * OPLANE + px]     = acc[j][nb][2 * h];
                        ob[(size_t)(nb * 8 + 1) * OPLANE + px] = acc[j][nb][2 * h + 1];
                    }
                }
        }
    } else {
        // ==== PRODUCERS: 4 warps, rolling 1-row stage, 4-deep lead ====
        const int ptid = tid - 512;
        #pragma unroll 1
        for (int it = 0; it < TILES_PER_CTA; ++it) {
            const int t  = t0 + it;
            const int g  = t / WH_OUT;
            const int y  = t - g * WH_OUT;
            const int b  = g >> 1;
            const int xs = (g & 1) ? 92 : 0;

            if (y == 0 && it > 0) BAR_SYNC(9, NTHREADS);  // boundary rendezvous
            if (it >= 4) BAR_SYNC(5 + (it & 3), 384);     // ring slot free (tile it-4 done)

            if (it == 0 || y == 0) {
                stage_row(x, b, xs, y + 0, a_sm, ptid);
                stage_row(x, b, xs, y + 1, a_sm, ptid);
                stage_row(x, b, xs, y + 2, a_sm, ptid);
            } else {
                stage_row(x, b, xs, y + 2, a_sm, ptid);
            }
            MEMBAR_CTA();
            BAR_ARRIVE(1 + (it & 3), 384);                // rows staged for tile it
        }
    }
}

extern "C" void kernel_launch(void* const* d_in, const int* in_sizes, int n_in,
                              void* d_out, int out_size)
{
    const float* x = (const float*)d_in[0];
    const float* w = (const float*)d_in[1];
    float* out = (float*)d_out;

    static bool attr_set = false;
    if (!attr_set) {
        cudaFuncSetAttribute(quanv_w20_kernel,
                             cudaFuncAttributeMaxDynamicSharedMemorySize, SMEM_BYTES);
        attr_set = true;
    }
    quanv_w20_kernel<<<148, NTHREADS, SMEM_BYTES>>>(x, w, out);
}